// round 2
// baseline (speedup 1.0000x reference)
#include <cuda_runtime.h>
#include <math.h>

#define CCH 128      // channels
#define NSP 4096     // spatial tokens (16*16*16)
#define NB 2         // batch
#define NG 32        // groups
#define QT 64        // query tile
#define KTL 64       // key tile
#define PSROW 68     // padded row for p tile (avoids bank conflicts in PV reads)

// ---------------- scratch (device globals; no allocation allowed) -------------
__device__ float g_wT[4 * CCH * CCH];      // [mat][c][o]  (transposed weights)
__device__ float g_q [NB * CCH * NSP];     // [b][c][n]
__device__ float g_k [NB * CCH * NSP];     // [b][c][n]
__device__ float g_vT[NB * NSP * CCH];     // [b][n][c]
__device__ float g_h [NB * CCH * NSP];     // [b][c][n]  attention output (pre out-proj)
__device__ float g_x [NB * CCH * NSP];     // [b][c][n]  out-proj + residual
__device__ float g_mu[NB * NG];
__device__ float g_rs[NB * NG];

// ---------------- K0: transpose the 4 weight matrices -------------------------
__global__ void k_transpose_w(const float* __restrict__ wq, const float* __restrict__ wk,
                              const float* __restrict__ wv, const float* __restrict__ wo)
{
    __shared__ float tile[32][33];
    const float* W = (blockIdx.z == 0) ? wq : (blockIdx.z == 1) ? wk
                     : (blockIdx.z == 2) ? wv : wo;
    float* out = g_wT + blockIdx.z * CCH * CCH;
    int bx = blockIdx.x * 32, by = blockIdx.y * 32;
    int tx = threadIdx.x, ty = threadIdx.y;
    #pragma unroll
    for (int k = 0; k < 32; k += 8)
        tile[ty + k][tx] = W[(by + ty + k) * CCH + bx + tx];
    __syncthreads();
    #pragma unroll
    for (int k = 0; k < 32; k += 8)
        out[(bx + ty + k) * CCH + by + tx] = tile[tx][ty + k];
}

// ---------------- K1: QKV projections -----------------------------------------
// out[b,o,n] = sum_c W[o,c] * in[b,c,n] + bias[o]
// z=0 -> q [b][c][n], z=1 -> k [b][c][n], z=2 -> v transposed [b][n][c]
__global__ __launch_bounds__(256) void k_proj_qkv(
    const float* __restrict__ query, const float* __restrict__ key,
    const float* __restrict__ value,
    const float* __restrict__ bq, const float* __restrict__ bk,
    const float* __restrict__ bv)
{
    extern __shared__ float sm[];
    float* WT = sm;               // [c][o] 128x128
    float* xs = sm + CCH * CCH;   // [c][64]
    int z = blockIdx.z;
    const float* x    = (z == 0) ? query : (z == 1) ? key : value;
    const float* bias = (z == 0) ? bq    : (z == 1) ? bk  : bv;
    const float* WTg  = g_wT + z * CCH * CCH;
    int b  = blockIdx.y;
    int n0 = blockIdx.x * 64;
    int t  = threadIdx.x;

    for (int i = t; i < CCH * CCH / 4; i += 256)
        ((float4*)WT)[i] = ((const float4*)WTg)[i];
    for (int i = t; i < CCH * 16; i += 256) {
        int c = i >> 4, no = (i & 15) * 4;
        *(float4*)&xs[c * 64 + no] =
            *(const float4*)&x[(b * CCH + c) * NSP + n0 + no];
    }
    __syncthreads();

    int nn = (t & 7) * 8;
    int oo = (t >> 3) * 4;
    float acc[4][8];
    #pragma unroll
    for (int i = 0; i < 4; i++) {
        float bb = bias[oo + i];
        #pragma unroll
        for (int j = 0; j < 8; j++) acc[i][j] = bb;
    }

    #pragma unroll 4
    for (int c = 0; c < CCH; c++) {
        float4 w4 = *(float4*)&WT[c * CCH + oo];
        float4 xa = *(float4*)&xs[c * 64 + nn];
        float4 xb = *(float4*)&xs[c * 64 + nn + 4];
        float wr[4] = {w4.x, w4.y, w4.z, w4.w};
        float xv[8] = {xa.x, xa.y, xa.z, xa.w, xb.x, xb.y, xb.z, xb.w};
        #pragma unroll
        for (int i = 0; i < 4; i++)
            #pragma unroll
            for (int j = 0; j < 8; j++) acc[i][j] += wr[i] * xv[j];
    }

    if (z < 2) {
        float* out = (z == 0) ? g_q : g_k;
        #pragma unroll
        for (int i = 0; i < 4; i++) {
            int addr = (b * CCH + oo + i) * NSP + n0 + nn;
            *(float4*)&out[addr]     = make_float4(acc[i][0], acc[i][1], acc[i][2], acc[i][3]);
            *(float4*)&out[addr + 4] = make_float4(acc[i][4], acc[i][5], acc[i][6], acc[i][7]);
        }
    } else {
        #pragma unroll
        for (int j = 0; j < 8; j++) {
            *(float4*)&g_vT[(b * NSP + n0 + nn + j) * CCH + oo] =
                make_float4(acc[0][j], acc[1][j], acc[2][j], acc[3][j]);
        }
    }
}

// ---------------- K2: flash attention ------------------------------------------
// h[b,c,i] = sum_j softmax_j(q[b,:,i]·k[b,:,j]) * v[b,c,j]
__global__ __launch_bounds__(256, 1) void k_attn()
{
    extern __shared__ float sm[];
    float* qs      = sm;                        // [128][64]  (c-major)
    float* ks      = qs + CCH * QT;             // [128][64]
    float* vs      = ks + CCH * KTL;            // [64][128]  (kt-major)
    float* ps      = vs + KTL * CCH;            // [64][PSROW]
    float* scale_s = ps + QT * PSROW;           // [64]
    float* l_s     = scale_s + QT;              // [64]

    int b  = blockIdx.y;
    int i0 = blockIdx.x * QT;
    int t  = threadIdx.x;
    int lane = t & 31, w = t >> 5;

    for (int i = t; i < CCH * QT / 4; i += 256) {
        int c = i >> 4, qo = (i & 15) * 4;
        *(float4*)&qs[c * QT + qo] =
            *(const float4*)&g_q[(b * CCH + c) * NSP + i0 + qo];
    }

    // QK mapping: warp w owns rows [w*8, w*8+8); each half-warp owns 4 rows
    int qt0 = w * 8 + (lane >> 4) * 4;
    int kt0 = (lane & 15) * 4;
    // PV mapping: thread owns 4 rows x 8 channels
    int qt0p = (t >> 4) * 4;
    int c0   = (t & 15) * 4;

    float m[4], l[4];
    float acc[4][8];
    #pragma unroll
    for (int r = 0; r < 4; r++) {
        m[r] = -1e30f; l[r] = 0.f;
        #pragma unroll
        for (int j = 0; j < 8; j++) acc[r][j] = 0.f;
    }

    for (int jt = 0; jt < NSP / KTL; jt++) {
        int j0 = jt * KTL;
        __syncthreads();                 // prev iter's PV done before reuse
        for (int i = t; i < CCH * KTL / 4; i += 256) {
            int c = i >> 4, ko = (i & 15) * 4;
            *(float4*)&ks[c * KTL + ko] =
                *(const float4*)&g_k[(b * CCH + c) * NSP + j0 + ko];
        }
        for (int i = t; i < KTL * CCH / 4; i += 256) {
            int kt = i >> 5, co = (i & 31) * 4;
            *(float4*)&vs[kt * CCH + co] =
                *(const float4*)&g_vT[(b * NSP + j0 + kt) * CCH + co];
        }
        __syncthreads();

        // --- QK: s[4q][4k] micro-tile ---
        float s[4][4];
        #pragma unroll
        for (int r = 0; r < 4; r++)
            #pragma unroll
            for (int cc = 0; cc < 4; cc++) s[r][cc] = 0.f;

        #pragma unroll 4
        for (int c = 0; c < CCH; c++) {
            float4 q4 = *(float4*)&qs[c * QT + qt0];
            float4 k4 = *(float4*)&ks[c * KTL + kt0];
            float qv[4] = {q4.x, q4.y, q4.z, q4.w};
            float kv[4] = {k4.x, k4.y, k4.z, k4.w};
            #pragma unroll
            for (int r = 0; r < 4; r++)
                #pragma unroll
                for (int cc = 0; cc < 4; cc++) s[r][cc] += qv[r] * kv[cc];
        }

        // --- online softmax (rows live in 16-lane half-warps) ---
        float sc_loc[4];
        #pragma unroll
        for (int r = 0; r < 4; r++) {
            float mx = fmaxf(fmaxf(s[r][0], s[r][1]), fmaxf(s[r][2], s[r][3]));
            mx = fmaxf(mx, __shfl_xor_sync(0xffffffffu, mx, 8));
            mx = fmaxf(mx, __shfl_xor_sync(0xffffffffu, mx, 4));
            mx = fmaxf(mx, __shfl_xor_sync(0xffffffffu, mx, 2));
            mx = fmaxf(mx, __shfl_xor_sync(0xffffffffu, mx, 1));
            float mn = fmaxf(m[r], mx);
            float sum = 0.f;
            #pragma unroll
            for (int cc = 0; cc < 4; cc++) {
                float p = __expf(s[r][cc] - mn);
                s[r][cc] = p; sum += p;
            }
            sum += __shfl_xor_sync(0xffffffffu, sum, 8);
            sum += __shfl_xor_sync(0xffffffffu, sum, 4);
            sum += __shfl_xor_sync(0xffffffffu, sum, 2);
            sum += __shfl_xor_sync(0xffffffffu, sum, 1);
            float scl = __expf(m[r] - mn);
            l[r] = l[r] * scl + sum;
            m[r] = mn;
            sc_loc[r] = scl;
            *(float4*)&ps[(qt0 + r) * PSROW + kt0] =
                make_float4(s[r][0], s[r][1], s[r][2], s[r][3]);
        }
        if ((lane & 15) == 0) {
            #pragma unroll
            for (int r = 0; r < 4; r++) scale_s[qt0 + r] = sc_loc[r];
        }
        __syncthreads();

        // --- PV: acc[4q][8c] += p · v ---
        #pragma unroll
        for (int r = 0; r < 4; r++) {
            float scl = scale_s[qt0p + r];
            #pragma unroll
            for (int j = 0; j < 8; j++) acc[r][j] *= scl;
        }
        for (int kt = 0; kt < KTL; kt += 4) {
            float pr[4][4];
            #pragma unroll
            for (int r = 0; r < 4; r++) {
                float4 p4 = *(float4*)&ps[(qt0p + r) * PSROW + kt];
                pr[r][0] = p4.x; pr[r][1] = p4.y; pr[r][2] = p4.z; pr[r][3] = p4.w;
            }
            #pragma unroll
            for (int u = 0; u < 4; u++) {
                float4 va = *(float4*)&vs[(kt + u) * CCH + c0];
                float4 vb = *(float4*)&vs[(kt + u) * CCH + c0 + 64];
                float vvv[8] = {va.x, va.y, va.z, va.w, vb.x, vb.y, vb.z, vb.w};
                #pragma unroll
                for (int r = 0; r < 4; r++)
                    #pragma unroll
                    for (int j = 0; j < 8; j++) acc[r][j] += pr[r][u] * vvv[j];
            }
        }
    }

    if ((lane & 15) == 0) {
        #pragma unroll
        for (int r = 0; r < 4; r++) l_s[qt0 + r] = l[r];
    }
    __syncthreads();
    #pragma unroll
    for (int r = 0; r < 4; r++) {
        float inv = 1.0f / l_s[qt0p + r];
        int qi = i0 + qt0p + r;
        #pragma unroll
        for (int j = 0; j < 4; j++) {
            g_h[(b * CCH + c0 + j) * NSP + qi]      = acc[r][j]     * inv;
            g_h[(b * CCH + c0 + 64 + j) * NSP + qi] = acc[r][j + 4] * inv;
        }
    }
}

// ---------------- K3: output projection + residual -----------------------------
__global__ __launch_bounds__(256) void k_oproj(const float* __restrict__ value,
                                               const float* __restrict__ bo)
{
    extern __shared__ float sm[];
    float* WT = sm;
    float* xs = sm + CCH * CCH;
    const float* WTg = g_wT + 3 * CCH * CCH;
    int b  = blockIdx.y;
    int n0 = blockIdx.x * 64;
    int t  = threadIdx.x;

    for (int i = t; i < CCH * CCH / 4; i += 256)
        ((float4*)WT)[i] = ((const float4*)WTg)[i];
    for (int i = t; i < CCH * 16; i += 256) {
        int c = i >> 4, no = (i & 15) * 4;
        *(float4*)&xs[c * 64 + no] =
            *(const float4*)&g_h[(b * CCH + c) * NSP + n0 + no];
    }
    __syncthreads();

    int nn = (t & 7) * 8;
    int oo = (t >> 3) * 4;
    float acc[4][8];
    #pragma unroll
    for (int i = 0; i < 4; i++) {
        float bb = bo[oo + i];
        #pragma unroll
        for (int j = 0; j < 8; j++) acc[i][j] = bb;
    }
    #pragma unroll 4
    for (int c = 0; c < CCH; c++) {
        float4 w4 = *(float4*)&WT[c * CCH + oo];
        float4 xa = *(float4*)&xs[c * 64 + nn];
        float4 xb = *(float4*)&xs[c * 64 + nn + 4];
        float wr[4] = {w4.x, w4.y, w4.z, w4.w};
        float xv[8] = {xa.x, xa.y, xa.z, xa.w, xb.x, xb.y, xb.z, xb.w};
        #pragma unroll
        for (int i = 0; i < 4; i++)
            #pragma unroll
            for (int j = 0; j < 8; j++) acc[i][j] += wr[i] * xv[j];
    }
    #pragma unroll
    for (int i = 0; i < 4; i++) {
        int addr = (b * CCH + oo + i) * NSP + n0 + nn;
        float4 v0 = *(const float4*)&value[addr];
        float4 v1 = *(const float4*)&value[addr + 4];
        *(float4*)&g_x[addr] =
            make_float4(acc[i][0] + v0.x, acc[i][1] + v0.y, acc[i][2] + v0.z, acc[i][3] + v0.w);
        *(float4*)&g_x[addr + 4] =
            make_float4(acc[i][4] + v1.x, acc[i][5] + v1.y, acc[i][6] + v1.z, acc[i][7] + v1.w);
    }
}

// ---------------- K4: groupnorm statistics --------------------------------------
__global__ void k_gnstats()
{
    int bg = blockIdx.x;                       // b*32 + g
    const float* xp = g_x + (size_t)bg * 4 * NSP;
    float s = 0.f, s2 = 0.f;
    for (int i = threadIdx.x; i < 4 * NSP / 4; i += blockDim.x) {
        float4 v = ((const float4*)xp)[i];
        s  += v.x + v.y + v.z + v.w;
        s2 += v.x * v.x + v.y * v.y + v.z * v.z + v.w * v.w;
    }
    __shared__ float rs1[8], rs2[8];
    #pragma unroll
    for (int o = 16; o > 0; o >>= 1) {
        s  += __shfl_xor_sync(0xffffffffu, s, o);
        s2 += __shfl_xor_sync(0xffffffffu, s2, o);
    }
    int lane = threadIdx.x & 31, wid = threadIdx.x >> 5;
    if (lane == 0) { rs1[wid] = s; rs2[wid] = s2; }
    __syncthreads();
    if (wid == 0) {
        s  = (lane < 8) ? rs1[lane] : 0.f;
        s2 = (lane < 8) ? rs2[lane] : 0.f;
        #pragma unroll
        for (int o = 4; o > 0; o >>= 1) {
            s  += __shfl_xor_sync(0xffffffffu, s, o);
            s2 += __shfl_xor_sync(0xffffffffu, s2, o);
        }
        if (lane == 0) {
            float inv = 1.0f / (4.0f * NSP);
            float mu = s * inv;
            float var = s2 * inv - mu * mu;
            g_mu[bg] = mu;
            g_rs[bg] = rsqrtf(var + 1e-5f);
        }
    }
}

// ---------------- K5: y = GN(x); out = y * sigmoid(y) ---------------------------
__global__ void k_silu_out(const float* __restrict__ gamma,
                           const float* __restrict__ beta,
                           float* __restrict__ out)
{
    int f = blockIdx.x * blockDim.x + threadIdx.x;      // float4 index
    if (f >= NB * CCH * NSP / 4) return;
    int c  = (f >> 10) & 127;                           // 4096/4 = 1024 float4 per row
    int bg = (f >> 17) * NG + (c >> 2);                 // 128*1024 float4 per batch
    float mu = g_mu[bg], rs = g_rs[bg];
    float ga = gamma[c] * rs;
    float be = beta[c] - mu * ga;
    float4 v = ((const float4*)g_x)[f];
    float4 o;
    float y;
    y = v.x * ga + be; o.x = y / (1.0f + __expf(-y));
    y = v.y * ga + be; o.y = y / (1.0f + __expf(-y));
    y = v.z * ga + be; o.z = y / (1.0f + __expf(-y));
    y = v.w * ga + be; o.w = y / (1.0f + __expf(-y));
    ((float4*)out)[f] = o;
}

// ---------------- launch --------------------------------------------------------
extern "C" void kernel_launch(void* const* d_in, const int* in_sizes, int n_in,
                              void* d_out, int out_size)
{
    const float* query = (const float*)d_in[0];
    const float* key   = (const float*)d_in[1];
    const float* value = (const float*)d_in[2];
    const float* wq    = (const float*)d_in[3];
    const float* bq    = (const float*)d_in[4];
    const float* wk    = (const float*)d_in[5];
    const float* bk    = (const float*)d_in[6];
    const float* wv    = (const float*)d_in[7];
    const float* bv    = (const float*)d_in[8];
    const float* wo    = (const float*)d_in[9];
    const float* bo    = (const float*)d_in[10];
    const float* gamma = (const float*)d_in[11];
    const float* beta  = (const float*)d_in[12];
    float* out = (float*)d_out;

    int smem_proj = (CCH * CCH + CCH * 64) * 4;                                   // 96 KB
    int smem_attn = (CCH * QT + CCH * KTL + KTL * CCH + QT * PSROW + 2 * QT) * 4; // ~113.5 KB
    cudaFuncSetAttribute(k_proj_qkv, cudaFuncAttributeMaxDynamicSharedMemorySize, smem_proj);
    cudaFuncSetAttribute(k_oproj,    cudaFuncAttributeMaxDynamicSharedMemorySize, smem_proj);
    cudaFuncSetAttribute(k_attn,     cudaFuncAttributeMaxDynamicSharedMemorySize, smem_attn);

    k_transpose_w<<<dim3(4, 4, 4), dim3(32, 8)>>>(wq, wk, wv, wo);
    k_proj_qkv<<<dim3(64, NB, 3), 256, smem_proj>>>(query, key, value, bq, bk, bv);
    k_attn<<<dim3(NSP / QT, NB), 256, smem_attn>>>();
    k_oproj<<<dim3(64, NB), 256, smem_proj>>>(value, bo);
    k_gnstats<<<dim3(NB * NG), 256>>>();
    k_silu_out<<<dim3(NB * CCH * NSP / 4 / 256), 256>>>(gamma, beta, out);
}

// round 3
// speedup vs baseline: 1.0202x; 1.0202x over previous
#include <cuda_runtime.h>
#include <math.h>

#define CCH 128      // channels
#define NSP 4096     // spatial tokens (16*16*16)
#define NB 2         // batch
#define NG 32        // groups
#define QT 64        // query tile
#define KTL 64       // key tile
#define PSROW 68     // padded row for p tile (avoids bank conflicts in PV reads)

// ---------------- scratch (device globals; no allocation allowed) -------------
__device__ float g_wT[4 * CCH * CCH];      // [mat][c][o]  (transposed weights)
__device__ float g_q [NB * CCH * NSP];     // [b][c][n]
__device__ float g_k [NB * CCH * NSP];     // [b][c][n]
__device__ float g_vT[NB * NSP * CCH];     // [b][n][c]
__device__ float g_h [NB * CCH * NSP];     // [b][c][n]  attention output (pre out-proj)
__device__ float g_x [NB * CCH * NSP];     // [b][c][n]  out-proj + residual
__device__ float g_mu[NB * NG];
__device__ float g_rs[NB * NG];

// ---------------- K0: transpose the 4 weight matrices -------------------------
__global__ void k_transpose_w(const float* __restrict__ wq, const float* __restrict__ wk,
                              const float* __restrict__ wv, const float* __restrict__ wo)
{
    __shared__ float tile[32][33];
    const float* W = (blockIdx.z == 0) ? wq : (blockIdx.z == 1) ? wk
                     : (blockIdx.z == 2) ? wv : wo;
    float* out = g_wT + blockIdx.z * CCH * CCH;
    int bx = blockIdx.x * 32, by = blockIdx.y * 32;
    int tx = threadIdx.x, ty = threadIdx.y;
    #pragma unroll
    for (int k = 0; k < 32; k += 8)
        tile[ty + k][tx] = W[(by + ty + k) * CCH + bx + tx];
    __syncthreads();
    #pragma unroll
    for (int k = 0; k < 32; k += 8)
        out[(bx + ty + k) * CCH + by + tx] = tile[tx][ty + k];
}

// ---------------- K1: QKV projections -----------------------------------------
// out[b,o,n] = sum_c W[o,c] * in[b,c,n] + bias[o]
// z=0 -> q [b][c][n], z=1 -> k [b][c][n], z=2 -> v transposed [b][n][c]
__global__ __launch_bounds__(256) void k_proj_qkv(
    const float* __restrict__ query, const float* __restrict__ key,
    const float* __restrict__ value,
    const float* __restrict__ bq, const float* __restrict__ bk,
    const float* __restrict__ bv)
{
    extern __shared__ float sm[];
    float* WT = sm;               // [c][o] 128x128
    float* xs = sm + CCH * CCH;   // [c][64]
    int z = blockIdx.z;
    const float* x    = (z == 0) ? query : (z == 1) ? key : value;
    const float* bias = (z == 0) ? bq    : (z == 1) ? bk  : bv;
    const float* WTg  = g_wT + z * CCH * CCH;
    int b  = blockIdx.y;
    int n0 = blockIdx.x * 64;
    int t  = threadIdx.x;

    for (int i = t; i < CCH * CCH / 4; i += 256)
        ((float4*)WT)[i] = ((const float4*)WTg)[i];
    for (int i = t; i < CCH * 16; i += 256) {
        int c = i >> 4, no = (i & 15) * 4;
        *(float4*)&xs[c * 64 + no] =
            *(const float4*)&x[(b * CCH + c) * NSP + n0 + no];
    }
    __syncthreads();

    int nn = (t & 7) * 8;
    int oo = (t >> 3) * 4;
    float acc[4][8];
    #pragma unroll
    for (int i = 0; i < 4; i++) {
        float bb = bias[oo + i];
        #pragma unroll
        for (int j = 0; j < 8; j++) acc[i][j] = bb;
    }

    #pragma unroll 4
    for (int c = 0; c < CCH; c++) {
        float4 w4 = *(float4*)&WT[c * CCH + oo];
        float4 xa = *(float4*)&xs[c * 64 + nn];
        float4 xb = *(float4*)&xs[c * 64 + nn + 4];
        float wr[4] = {w4.x, w4.y, w4.z, w4.w};
        float xv[8] = {xa.x, xa.y, xa.z, xa.w, xb.x, xb.y, xb.z, xb.w};
        #pragma unroll
        for (int i = 0; i < 4; i++)
            #pragma unroll
            for (int j = 0; j < 8; j++) acc[i][j] += wr[i] * xv[j];
    }

    if (z < 2) {
        float* out = (z == 0) ? g_q : g_k;
        #pragma unroll
        for (int i = 0; i < 4; i++) {
            int addr = (b * CCH + oo + i) * NSP + n0 + nn;
            *(float4*)&out[addr]     = make_float4(acc[i][0], acc[i][1], acc[i][2], acc[i][3]);
            *(float4*)&out[addr + 4] = make_float4(acc[i][4], acc[i][5], acc[i][6], acc[i][7]);
        }
    } else {
        #pragma unroll
        for (int j = 0; j < 8; j++) {
            *(float4*)&g_vT[(b * NSP + n0 + nn + j) * CCH + oo] =
                make_float4(acc[0][j], acc[1][j], acc[2][j], acc[3][j]);
        }
    }
}

// ---------------- K2: flash attention ------------------------------------------
// h[b,c,i] = sum_j softmax_j(q[b,:,i]·k[b,:,j]) * v[b,c,j]
__global__ __launch_bounds__(256, 1) void k_attn()
{
    extern __shared__ float sm[];
    float* qs      = sm;                        // [128][64]  (c-major)
    float* ks      = qs + CCH * QT;             // [128][64]
    float* vs      = ks + CCH * KTL;            // [64][128]  (kt-major)
    float* ps      = vs + KTL * CCH;            // [64][PSROW]
    float* scale_s = ps + QT * PSROW;           // [64]
    float* l_s     = scale_s + QT;              // [64]

    int b  = blockIdx.y;
    int i0 = blockIdx.x * QT;
    int t  = threadIdx.x;
    int lane = t & 31, w = t >> 5;

    for (int i = t; i < CCH * QT / 4; i += 256) {
        int c = i >> 4, qo = (i & 15) * 4;
        *(float4*)&qs[c * QT + qo] =
            *(const float4*)&g_q[(b * CCH + c) * NSP + i0 + qo];
    }

    // QK mapping: warp w owns rows [w*8, w*8+8); each half-warp owns 4 rows
    int qt0 = w * 8 + (lane >> 4) * 4;
    int kt0 = (lane & 15) * 4;
    // PV mapping: thread owns 4 rows x 8 channels
    int qt0p = (t >> 4) * 4;
    int c0   = (t & 15) * 4;

    float m[4], l[4];
    float acc[4][8];
    #pragma unroll
    for (int r = 0; r < 4; r++) {
        m[r] = -1e30f; l[r] = 0.f;
        #pragma unroll
        for (int j = 0; j < 8; j++) acc[r][j] = 0.f;
    }

    for (int jt = 0; jt < NSP / KTL; jt++) {
        int j0 = jt * KTL;
        __syncthreads();                 // prev iter's PV done before reuse
        for (int i = t; i < CCH * KTL / 4; i += 256) {
            int c = i >> 4, ko = (i & 15) * 4;
            *(float4*)&ks[c * KTL + ko] =
                *(const float4*)&g_k[(b * CCH + c) * NSP + j0 + ko];
        }
        for (int i = t; i < KTL * CCH / 4; i += 256) {
            int kt = i >> 5, co = (i & 31) * 4;
            *(float4*)&vs[kt * CCH + co] =
                *(const float4*)&g_vT[(b * NSP + j0 + kt) * CCH + co];
        }
        __syncthreads();

        // --- QK: s[4q][4k] micro-tile ---
        float s[4][4];
        #pragma unroll
        for (int r = 0; r < 4; r++)
            #pragma unroll
            for (int cc = 0; cc < 4; cc++) s[r][cc] = 0.f;

        #pragma unroll 4
        for (int c = 0; c < CCH; c++) {
            float4 q4 = *(float4*)&qs[c * QT + qt0];
            float4 k4 = *(float4*)&ks[c * KTL + kt0];
            float qv[4] = {q4.x, q4.y, q4.z, q4.w};
            float kv[4] = {k4.x, k4.y, k4.z, k4.w};
            #pragma unroll
            for (int r = 0; r < 4; r++)
                #pragma unroll
                for (int cc = 0; cc < 4; cc++) s[r][cc] += qv[r] * kv[cc];
        }

        // --- online softmax (rows live in 16-lane half-warps) ---
        float sc_loc[4];
        #pragma unroll
        for (int r = 0; r < 4; r++) {
            float mx = fmaxf(fmaxf(s[r][0], s[r][1]), fmaxf(s[r][2], s[r][3]));
            mx = fmaxf(mx, __shfl_xor_sync(0xffffffffu, mx, 8));
            mx = fmaxf(mx, __shfl_xor_sync(0xffffffffu, mx, 4));
            mx = fmaxf(mx, __shfl_xor_sync(0xffffffffu, mx, 2));
            mx = fmaxf(mx, __shfl_xor_sync(0xffffffffu, mx, 1));
            float mn = fmaxf(m[r], mx);
            float sum = 0.f;
            #pragma unroll
            for (int cc = 0; cc < 4; cc++) {
                float p = __expf(s[r][cc] - mn);
                s[r][cc] = p; sum += p;
            }
            sum += __shfl_xor_sync(0xffffffffu, sum, 8);
            sum += __shfl_xor_sync(0xffffffffu, sum, 4);
            sum += __shfl_xor_sync(0xffffffffu, sum, 2);
            sum += __shfl_xor_sync(0xffffffffu, sum, 1);
            float scl = __expf(m[r] - mn);
            l[r] = l[r] * scl + sum;
            m[r] = mn;
            sc_loc[r] = scl;
            *(float4*)&ps[(qt0 + r) * PSROW + kt0] =
                make_float4(s[r][0], s[r][1], s[r][2], s[r][3]);
        }
        if ((lane & 15) == 0) {
            #pragma unroll
            for (int r = 0; r < 4; r++) scale_s[qt0 + r] = sc_loc[r];
        }
        __syncthreads();

        // --- PV: acc[4q][8c] += p · v ---
        #pragma unroll
        for (int r = 0; r < 4; r++) {
            float scl = scale_s[qt0p + r];
            #pragma unroll
            for (int j = 0; j < 8; j++) acc[r][j] *= scl;
        }
        for (int kt = 0; kt < KTL; kt += 4) {
            float pr[4][4];
            #pragma unroll
            for (int r = 0; r < 4; r++) {
                float4 p4 = *(float4*)&ps[(qt0p + r) * PSROW + kt];
                pr[r][0] = p4.x; pr[r][1] = p4.y; pr[r][2] = p4.z; pr[r][3] = p4.w;
            }
            #pragma unroll
            for (int u = 0; u < 4; u++) {
                float4 va = *(float4*)&vs[(kt + u) * CCH + c0];
                float4 vb = *(float4*)&vs[(kt + u) * CCH + c0 + 64];
                float vvv[8] = {va.x, va.y, va.z, va.w, vb.x, vb.y, vb.z, vb.w};
                #pragma unroll
                for (int r = 0; r < 4; r++)
                    #pragma unroll
                    for (int j = 0; j < 8; j++) acc[r][j] += pr[r][u] * vvv[j];
            }
        }
    }

    if ((lane & 15) == 0) {
        #pragma unroll
        for (int r = 0; r < 4; r++) l_s[qt0 + r] = l[r];
    }
    __syncthreads();
    #pragma unroll
    for (int r = 0; r < 4; r++) {
        float inv = 1.0f / l_s[qt0p + r];
        int qi = i0 + qt0p + r;
        #pragma unroll
        for (int j = 0; j < 4; j++) {
            g_h[(b * CCH + c0 + j) * NSP + qi]      = acc[r][j]     * inv;
            g_h[(b * CCH + c0 + 64 + j) * NSP + qi] = acc[r][j + 4] * inv;
        }
    }
}

// ---------------- K3: output projection + residual -----------------------------
__global__ __launch_bounds__(256) void k_oproj(const float* __restrict__ value,
                                               const float* __restrict__ bo)
{
    extern __shared__ float sm[];
    float* WT = sm;
    float* xs = sm + CCH * CCH;
    const float* WTg = g_wT + 3 * CCH * CCH;
    int b  = blockIdx.y;
    int n0 = blockIdx.x * 64;
    int t  = threadIdx.x;

    for (int i = t; i < CCH * CCH / 4; i += 256)
        ((float4*)WT)[i] = ((const float4*)WTg)[i];
    for (int i = t; i < CCH * 16; i += 256) {
        int c = i >> 4, no = (i & 15) * 4;
        *(float4*)&xs[c * 64 + no] =
            *(const float4*)&g_h[(b * CCH + c) * NSP + n0 + no];
    }
    __syncthreads();

    int nn = (t & 7) * 8;
    int oo = (t >> 3) * 4;
    float acc[4][8];
    #pragma unroll
    for (int i = 0; i < 4; i++) {
        float bb = bo[oo + i];
        #pragma unroll
        for (int j = 0; j < 8; j++) acc[i][j] = bb;
    }
    #pragma unroll 4
    for (int c = 0; c < CCH; c++) {
        float4 w4 = *(float4*)&WT[c * CCH + oo];
        float4 xa = *(float4*)&xs[c * 64 + nn];
        float4 xb = *(float4*)&xs[c * 64 + nn + 4];
        float wr[4] = {w4.x, w4.y, w4.z, w4.w};
        float xv[8] = {xa.x, xa.y, xa.z, xa.w, xb.x, xb.y, xb.z, xb.w};
        #pragma unroll
        for (int i = 0; i < 4; i++)
            #pragma unroll
            for (int j = 0; j < 8; j++) acc[i][j] += wr[i] * xv[j];
    }
    #pragma unroll
    for (int i = 0; i < 4; i++) {
        int addr = (b * CCH + oo + i) * NSP + n0 + nn;
        float4 v0 = *(const float4*)&value[addr];
        float4 v1 = *(const float4*)&value[addr + 4];
        *(float4*)&g_x[addr] =
            make_float4(acc[i][0] + v0.x, acc[i][1] + v0.y, acc[i][2] + v0.z, acc[i][3] + v0.w);
        *(float4*)&g_x[addr + 4] =
            make_float4(acc[i][4] + v1.x, acc[i][5] + v1.y, acc[i][6] + v1.z, acc[i][7] + v1.w);
    }
}

// ---------------- K4: groupnorm statistics --------------------------------------
__global__ void k_gnstats()
{
    int bg = blockIdx.x;                       // b*32 + g
    const float* xp = g_x + (size_t)bg * 4 * NSP;
    float s = 0.f, s2 = 0.f;
    for (int i = threadIdx.x; i < 4 * NSP / 4; i += blockDim.x) {
        float4 v = ((const float4*)xp)[i];
        s  += v.x + v.y + v.z + v.w;
        s2 += v.x * v.x + v.y * v.y + v.z * v.z + v.w * v.w;
    }
    __shared__ float rs1[8], rs2[8];
    #pragma unroll
    for (int o = 16; o > 0; o >>= 1) {
        s  += __shfl_xor_sync(0xffffffffu, s, o);
        s2 += __shfl_xor_sync(0xffffffffu, s2, o);
    }
    int lane = threadIdx.x & 31, wid = threadIdx.x >> 5;
    if (lane == 0) { rs1[wid] = s; rs2[wid] = s2; }
    __syncthreads();
    if (wid == 0) {
        s  = (lane < 8) ? rs1[lane] : 0.f;
        s2 = (lane < 8) ? rs2[lane] : 0.f;
        #pragma unroll
        for (int o = 4; o > 0; o >>= 1) {
            s  += __shfl_xor_sync(0xffffffffu, s, o);
            s2 += __shfl_xor_sync(0xffffffffu, s2, o);
        }
        if (lane == 0) {
            float inv = 1.0f / (4.0f * NSP);
            float mu = s * inv;
            float var = s2 * inv - mu * mu;
            g_mu[bg] = mu;
            g_rs[bg] = rsqrtf(var + 1e-5f);
        }
    }
}

// ---------------- K5: y = GN(x); out = y * sigmoid(y) ---------------------------
__global__ void k_silu_out(const float* __restrict__ gamma,
                           const float* __restrict__ beta,
                           float* __restrict__ out)
{
    int f = blockIdx.x * blockDim.x + threadIdx.x;      // float4 index
    if (f >= NB * CCH * NSP / 4) return;
    int c  = (f >> 10) & 127;                           // 4096/4 = 1024 float4 per row
    int bg = (f >> 17) * NG + (c >> 2);                 // 128*1024 float4 per batch
    float mu = g_mu[bg], rs = g_rs[bg];
    float ga = gamma[c] * rs;
    float be = beta[c] - mu * ga;
    float4 v = ((const float4*)g_x)[f];
    float4 o;
    float y;
    y = v.x * ga + be; o.x = y / (1.0f + __expf(-y));
    y = v.y * ga + be; o.y = y / (1.0f + __expf(-y));
    y = v.z * ga + be; o.z = y / (1.0f + __expf(-y));
    y = v.w * ga + be; o.w = y / (1.0f + __expf(-y));
    ((float4*)out)[f] = o;
}

// ---------------- launch --------------------------------------------------------
extern "C" void kernel_launch(void* const* d_in, const int* in_sizes, int n_in,
                              void* d_out, int out_size)
{
    const float* query = (const float*)d_in[0];
    const float* key   = (const float*)d_in[1];
    const float* value = (const float*)d_in[2];
    const float* wq    = (const float*)d_in[3];
    const float* bq    = (const float*)d_in[4];
    const float* wk    = (const float*)d_in[5];
    const float* bk    = (const float*)d_in[6];
    const float* wv    = (const float*)d_in[7];
    const float* bv    = (const float*)d_in[8];
    const float* wo    = (const float*)d_in[9];
    const float* bo    = (const float*)d_in[10];
    const float* gamma = (const float*)d_in[11];
    const float* beta  = (const float*)d_in[12];
    float* out = (float*)d_out;

    int smem_proj = (CCH * CCH + CCH * 64) * 4;                                   // 96 KB
    int smem_attn = (CCH * QT + CCH * KTL + KTL * CCH + QT * PSROW + 2 * QT) * 4; // ~113.5 KB
    cudaFuncSetAttribute(k_proj_qkv, cudaFuncAttributeMaxDynamicSharedMemorySize, smem_proj);
    cudaFuncSetAttribute(k_oproj,    cudaFuncAttributeMaxDynamicSharedMemorySize, smem_proj);
    cudaFuncSetAttribute(k_attn,     cudaFuncAttributeMaxDynamicSharedMemorySize, smem_attn);

    k_transpose_w<<<dim3(4, 4, 4), dim3(32, 8)>>>(wq, wk, wv, wo);
    k_proj_qkv<<<dim3(64, NB, 3), 256, smem_proj>>>(query, key, value, bq, bk, bv);
    k_attn<<<dim3(NSP / QT, NB), 256, smem_attn>>>();
    k_oproj<<<dim3(64, NB), 256, smem_proj>>>(value, bo);
    k_gnstats<<<dim3(NB * NG), 256>>>();
    k_silu_out<<<dim3(NB * CCH * NSP / 4 / 256), 256>>>(gamma, beta, out);
}